// round 9
// baseline (speedup 1.0000x reference)
#include <cuda_runtime.h>
#include <cuda_fp16.h>
#include <cstddef>

#define HDIM 64
#define NU_MAX 100000
#define NP_MAX 50000
#define NT_MAX (NU_MAX + NP_MAX)
#define E_MAX  2000000
#define SCAN_TILE 1024
#define XS_STRIDE 68
#define FILLB_MAX 384

// ---------------- scratch (static device globals; no allocation) ----------------
__device__ int    g_cnt[NT_MAX + 1];
__device__ int    g_rp [NT_MAX + 1];
__device__ int    g_cur[NT_MAX];
__device__ int    g_bsum[256];
__device__ int    g_csr[2 * E_MAX];
__device__ __half g_yu_h[(size_t)NU_MAX * HDIM];
__device__ __half g_yp_h[(size_t)NP_MAX * HDIM];
__device__ float  g_aggu[(size_t)NU_MAX * HDIM];
__device__ float  g_aggp[(size_t)NP_MAX * HDIM];
__device__ float  g_hu  [(size_t)NU_MAX * HDIM];
__device__ float  g_hp  [(size_t)NP_MAX * HDIM];
__device__ float  g_hu2 [(size_t)NU_MAX * HDIM];
__device__ float  g_hp2 [(size_t)NP_MAX * HDIM];

// ---------------- f32x2 helpers ----------------
__device__ __forceinline__ unsigned long long dupf(float x) {
    unsigned long long r;
    asm("mov.b64 %0, {%1, %1};" : "=l"(r) : "f"(x));
    return r;
}
__device__ __forceinline__ void ffma2(unsigned long long& d, unsigned long long a,
                                      unsigned long long b) {
    asm("fma.rn.f32x2 %0, %1, %2, %0;" : "+l"(d) : "l"(a), "l"(b));
}
__device__ __forceinline__ float2 unpk(unsigned long long v) {
    float lo, hi;
    asm("mov.b64 {%0, %1}, %2;" : "=f"(lo), "=f"(hi) : "l"(v));
    return make_float2(lo, hi);
}

// ---------------- degree counts (int4 ILP) ----------------
__global__ void degree_kernel(const int* __restrict__ src, const int* __restrict__ dst,
                              int* __restrict__ cnt, int NP, int E) {
    int i = blockIdx.x * blockDim.x + threadIdx.x;
    int st = gridDim.x * blockDim.x;
    int n4 = E >> 2;
    const int4* s4 = (const int4*)src;
    const int4* d4 = (const int4*)dst;
    for (int e = i; e < n4; e += st) {
        int4 s = __ldg(&s4[e]);
        int4 d = __ldg(&d4[e]);
        atomicAdd(&cnt[d.x], 1); atomicAdd(&cnt[d.y], 1);
        atomicAdd(&cnt[d.z], 1); atomicAdd(&cnt[d.w], 1);
        atomicAdd(&cnt[NP + s.x], 1); atomicAdd(&cnt[NP + s.y], 1);
        atomicAdd(&cnt[NP + s.z], 1); atomicAdd(&cnt[NP + s.w], 1);
    }
    for (int e = 4 * n4 + i; e < E; e += st) {
        atomicAdd(&cnt[dst[e]], 1);
        atomicAdd(&cnt[NP + src[e]], 1);
    }
}

// ---------------- scan phase A: per-tile sums ----------------
__global__ void scanA(const int* __restrict__ in, int* __restrict__ bsum, int n) {
    __shared__ int sh[256];
    int t = threadIdx.x, b = blockIdx.x;
    int base = b * SCAN_TILE;
    int s = 0;
    for (int i = t; i < SCAN_TILE; i += 256) {
        int idx = base + i;
        s += (idx < n) ? in[idx] : 0;
    }
    sh[t] = s; __syncthreads();
    for (int o = 128; o; o >>= 1) {
        if (t < o) sh[t] += sh[t + o];
        __syncthreads();
    }
    if (t == 0) bsum[b] = sh[0];
}

// ---------------- scan phase C: offsets + tile scan; writes rp AND cur ----------------
__global__ void scanC2(const int* __restrict__ cnt, const int* __restrict__ bsum,
                       int* __restrict__ rp, int* __restrict__ cur, int n, int nb) {
    __shared__ int sh[256];
    __shared__ int s_off;
    int t = threadIdx.x, b = blockIdx.x;
    int part = 0;
    for (int i = t; i < b; i += 256) part += bsum[i];
    sh[t] = part; __syncthreads();
    for (int o = 128; o; o >>= 1) {
        if (t < o) sh[t] += sh[t + o];
        __syncthreads();
    }
    if (t == 0) s_off = sh[0];
    __syncthreads();
    int off = s_off;
    __syncthreads();

    int base = b * SCAN_TILE;
    int i0 = base + t * 4;
    int v0 = (i0     < n) ? cnt[i0]     : 0;
    int v1 = (i0 + 1 < n) ? cnt[i0 + 1] : 0;
    int v2 = (i0 + 2 < n) ? cnt[i0 + 2] : 0;
    int v3 = (i0 + 3 < n) ? cnt[i0 + 3] : 0;
    int local = v0 + v1 + v2 + v3;
    sh[t] = local; __syncthreads();
    for (int o = 1; o < 256; o <<= 1) {
        int x = 0;
        if (t >= o) x = sh[t - o];
        __syncthreads();
        sh[t] += x;
        __syncthreads();
    }
    int run = off + sh[t] - local;
    if (i0     < n) { rp[i0]     = run; cur[i0]     = run; } run += v0;
    if (i0 + 1 < n) { rp[i0 + 1] = run; cur[i0 + 1] = run; } run += v1;
    if (i0 + 2 < n) { rp[i0 + 2] = run; cur[i0 + 2] = run; } run += v2;
    if (i0 + 3 < n) { rp[i0 + 3] = run; cur[i0 + 3] = run; }
    if (b == 0 && t == 0) {
        int tot = 0;
        for (int i = 0; i < nb; i++) tot += bsum[i];
        rp[n] = tot;
    }
}

// ---------------- CSR fill body (int4 ILP; runs inside fat launch) ----------------
__device__ void fill_body(const int* __restrict__ src, const int* __restrict__ dst,
                          int* __restrict__ cur, int* __restrict__ csr,
                          int NP, int E, int fb, int nfill) {
    int i = fb * 256 + threadIdx.x;
    int st = nfill * 256;
    int n4 = E >> 2;
    const int4* s4 = (const int4*)src;
    const int4* d4 = (const int4*)dst;
    for (int e = i; e < n4; e += st) {
        int4 s = __ldg(&s4[e]);
        int4 d = __ldg(&d4[e]);
        csr[atomicAdd(&cur[d.x], 1)] = s.x;
        csr[atomicAdd(&cur[d.y], 1)] = s.y;
        csr[atomicAdd(&cur[d.z], 1)] = s.z;
        csr[atomicAdd(&cur[d.w], 1)] = s.w;
        csr[atomicAdd(&cur[NP + s.x], 1)] = d.x;
        csr[atomicAdd(&cur[NP + s.y], 1)] = d.y;
        csr[atomicAdd(&cur[NP + s.z], 1)] = d.z;
        csr[atomicAdd(&cur[NP + s.w], 1)] = d.w;
    }
    for (int e = 4 * n4 + i; e < E; e += st) {
        int s = src[e], d = dst[e];
        csr[atomicAdd(&cur[d], 1)]      = s;
        csr[atomicAdd(&cur[NP + s], 1)] = d;
    }
}

// ---------------- GEMM machinery (64x64 tile, f32x2 packed core) ----------------
struct Seg {
    const float* X; const float* W; const float* bias; const float* agg;
    float* outf; __half* outh; int M; int K; int relu;
};

__device__ __forceinline__ void stage_W(const float* W, float* Ws, int Kq /* K*16 */) {
    for (int i = threadIdx.x; i < Kq; i += 256)
        ((float4*)Ws)[i] = __ldg((const float4*)W + i);
}

__device__ __forceinline__ void stage_X(const float* X, float* Xs, int K, int M, int base) {
    int nq = K >> 2;
    int lg = (K == 128) ? 5 : 4;
    for (int i = threadIdx.x; i < (nq << 6); i += 256) {
        int r = i >> lg, kq = i & (nq - 1);
        int row = base + r;
        if (row >= M) row = M - 1;
        float4 v = __ldg((const float4*)(X + (size_t)row * K) + kq);
        int k = kq * 4;
        Xs[(k + 0) * XS_STRIDE + r] = v.x;
        Xs[(k + 1) * XS_STRIDE + r] = v.y;
        Xs[(k + 2) * XS_STRIDE + r] = v.z;
        Xs[(k + 3) * XS_STRIDE + r] = v.w;
    }
}

// A[0..3]: rows (r0,r0+1) packed, cols c0..c0+3 ; A[4..7]: rows (r0+2,r0+3)
__device__ __forceinline__ void mma64(const float* Xs, const float* Ws, int K,
                                      int r0, int c0, unsigned long long* A) {
    const float* xp = Xs + r0;
    const float* wp = Ws + c0;
#pragma unroll 4
    for (int kk = 0; kk < K; kk++) {
        ulonglong2 aa = *(const ulonglong2*)xp;
        float4 bw = *(const float4*)wp;
        unsigned long long b0 = dupf(bw.x), b1 = dupf(bw.y),
                           b2 = dupf(bw.z), b3 = dupf(bw.w);
        ffma2(A[0], aa.x, b0); ffma2(A[1], aa.x, b1);
        ffma2(A[2], aa.x, b2); ffma2(A[3], aa.x, b3);
        ffma2(A[4], aa.y, b0); ffma2(A[5], aa.y, b1);
        ffma2(A[6], aa.y, b2); ffma2(A[7], aa.y, b3);
        xp += XS_STRIDE; wp += 64;
    }
}

__device__ __forceinline__ void epi_out(const unsigned long long* A, const Seg& S, int base,
                                        int r0, int c0, float* Hs) {
    float4 bv = make_float4(0.f, 0.f, 0.f, 0.f);
    if (S.bias) bv = *(const float4*)(S.bias + c0);
    float2 p0 = unpk(A[0]), p1 = unpk(A[1]), p2 = unpk(A[2]), p3 = unpk(A[3]);
    float2 q0 = unpk(A[4]), q1 = unpk(A[5]), q2 = unpk(A[6]), q3 = unpk(A[7]);
    float vr[4][4] = {
        {p0.x, p1.x, p2.x, p3.x},
        {p0.y, p1.y, p2.y, p3.y},
        {q0.x, q1.x, q2.x, q3.x},
        {q0.y, q1.y, q2.y, q3.y},
    };
#pragma unroll
    for (int i = 0; i < 4; i++) {
        int row = base + r0 + i;
        if (row >= S.M) continue;
        float v0 = vr[i][0], v1 = vr[i][1], v2 = vr[i][2], v3 = vr[i][3];
        if (S.agg) {
            float4 av = *(const float4*)(S.agg + (size_t)row * 64 + c0);
            v0 += av.x; v1 += av.y; v2 += av.z; v3 += av.w;
        }
        v0 += bv.x; v1 += bv.y; v2 += bv.z; v3 += bv.w;
        if (S.relu) {
            v0 = fmaxf(v0, 0.f); v1 = fmaxf(v1, 0.f);
            v2 = fmaxf(v2, 0.f); v3 = fmaxf(v3, 0.f);
        }
        if (Hs) {
            Hs[(c0 + 0) * XS_STRIDE + r0 + i] = v0;
            Hs[(c0 + 1) * XS_STRIDE + r0 + i] = v1;
            Hs[(c0 + 2) * XS_STRIDE + r0 + i] = v2;
            Hs[(c0 + 3) * XS_STRIDE + r0 + i] = v3;
        }
        if (S.outh) {
            __half2 h0 = __floats2half2_rn(v0, v1);
            __half2 h1 = __floats2half2_rn(v2, v3);
            uint2 u;
            u.x = *(unsigned*)&h0;
            u.y = *(unsigned*)&h1;
            *(uint2*)(S.outh + (size_t)row * 64 + c0) = u;
        } else if (S.outf) {
            *(float4*)(S.outf + (size_t)row * 64 + c0) = make_float4(v0, v1, v2, v3);
        }
    }
}

// ---------------- FAT1: transform-1 GEMM (dual seg) ∪ fill_csr, role-interleaved ----
__global__ void gemm_fat1(Seg A, Seg B, int nblkA,
                          const int* __restrict__ src, const int* __restrict__ dst,
                          int* __restrict__ cur, int* __restrict__ csr,
                          int NP, int E, int nfill) {
    int bid = blockIdx.x;
    int q = bid / 6, r6 = bid - q * 6;
    if (r6 == 5 && q < nfill) {
        fill_body(src, dst, cur, csr, NP, E, q, nfill);
        return;
    }
    int gb = bid - min(q, nfill);
    bool isA = gb < nblkA;
    Seg S = isA ? A : B;
    int base = (isA ? gb : gb - nblkA) * 64;

    extern __shared__ float sm[];
    float* Ws = sm;
    float* Xs = sm + S.K * 64;
    stage_W(S.W, Ws, S.K * 16);
    stage_X(S.X, Xs, S.K, S.M, base);
    __syncthreads();

    int lane = threadIdx.x & 31, w = threadIdx.x >> 5;
    int r0 = (w & 1) * 32 + (lane & 7) * 4;
    int c0 = (w >> 1) * 16 + (lane >> 3) * 4;
    unsigned long long Ac[8] = {0, 0, 0, 0, 0, 0, 0, 0};
    mma64(Xs, Ws, S.K, r0, c0, Ac);
    epi_out(Ac, S, base, r0, c0, nullptr);
}

// ---------------- plain dual-seg GEMM (epilogue-2) ----------------
__global__ void gemm_dual(Seg A, Seg B, int nblkA) {
    bool isA = blockIdx.x < (unsigned)nblkA;
    Seg S = isA ? A : B;
    int base = (isA ? blockIdx.x : blockIdx.x - nblkA) * 64;

    extern __shared__ float sm[];
    float* Ws = sm;
    float* Xs = sm + S.K * 64;
    stage_W(S.W, Ws, S.K * 16);
    stage_X(S.X, Xs, S.K, S.M, base);
    __syncthreads();

    int lane = threadIdx.x & 31, w = threadIdx.x >> 5;
    int r0 = (w & 1) * 32 + (lane & 7) * 4;
    int c0 = (w >> 1) * 16 + (lane >> 3) * 4;
    unsigned long long Ac[8] = {0, 0, 0, 0, 0, 0, 0, 0};
    mma64(Xs, Ws, S.K, r0, c0, Ac);
    epi_out(Ac, S, base, r0, c0, nullptr);
}

// ---------------- FUSED: epilogue-1 (h) + transform-2 (y2 = h@W2, fp16) ----------------
__global__ void gemm_epi_trans(Seg A, Seg B, int nblkA,
                               const float* __restrict__ W2A, const float* __restrict__ W2B,
                               __half* __restrict__ y2A, __half* __restrict__ y2B) {
    bool isA = blockIdx.x < (unsigned)nblkA;
    Seg S = isA ? A : B;
    const float* W2 = isA ? W2A : W2B;
    __half* y2 = isA ? y2A : y2B;
    int base = (isA ? blockIdx.x : blockIdx.x - nblkA) * 64;

    extern __shared__ float sm[];
    float* Ws1 = sm;                    // K x 64
    float* Ws2 = sm + S.K * 64;         // 64 x 64
    float* Xs  = Ws2 + 4096;            // K x 68 (reused as Hs for pass 2)
    stage_W(S.W, Ws1, S.K * 16);
    stage_W(W2, Ws2, 64 * 16);
    stage_X(S.X, Xs, S.K, S.M, base);
    __syncthreads();

    int lane = threadIdx.x & 31, w = threadIdx.x >> 5;
    int r0 = (w & 1) * 32 + (lane & 7) * 4;
    int c0 = (w >> 1) * 16 + (lane >> 3) * 4;

    unsigned long long Ac[8] = {0, 0, 0, 0, 0, 0, 0, 0};
    mma64(Xs, Ws1, S.K, r0, c0, Ac);
    __syncthreads();                    // everyone done reading Xs before it becomes Hs
    epi_out(Ac, S, base, r0, c0, Xs);   // writes h to global AND stages Hs (k-major)
    __syncthreads();                    // Hs ready

    unsigned long long Ac2[8] = {0, 0, 0, 0, 0, 0, 0, 0};
    mma64(Xs, Ws2, 64, r0, c0, Ac2);
    Seg S2 = {};
    S2.M = S.M; S2.outh = y2;
    epi_out(Ac2, S2, base, r0, c0, nullptr);
}

// ---------------- gather-mean: warp per node, 2 edges in flight (fp16 y) ----------------
__global__ void gather_mean(const __half* __restrict__ yu, const __half* __restrict__ yp,
                            const int* __restrict__ csr, const int* __restrict__ rp,
                            float* __restrict__ aggp, float* __restrict__ aggu,
                            int NP, int NT) {
    int lane = threadIdx.x & 31;
    int warp = (blockIdx.x * blockDim.x + threadIdx.x) >> 5;
    int nw   = (gridDim.x * blockDim.x) >> 5;
    int f = lane & 15, par = lane >> 4;
    for (int g = warp; g < NT; g += nw) {
        int b = rp[g], e = rp[g + 1];
        const uint2* Y = (const uint2*)((g < NP) ? yu : yp);
        float* out = (g < NP) ? (aggp + (size_t)g * 64) : (aggu + (size_t)(g - NP) * 64);
        float ax = 0.f, ay = 0.f, az = 0.f, aw = 0.f;
        int j = b + par;
        for (; j + 2 < e; j += 4) {
            int s0 = __ldg(&csr[j]);
            int s1 = __ldg(&csr[j + 2]);
            uint2 v0 = __ldg(&Y[(size_t)s0 * 16 + f]);
            uint2 v1 = __ldg(&Y[(size_t)s1 * 16 + f]);
            float2 p0 = __half22float2(*(__half2*)&v0.x);
            float2 p1 = __half22float2(*(__half2*)&v0.y);
            float2 q0 = __half22float2(*(__half2*)&v1.x);
            float2 q1 = __half22float2(*(__half2*)&v1.y);
            ax += p0.x + q0.x; ay += p0.y + q0.y;
            az += p1.x + q1.x; aw += p1.y + q1.y;
        }
        if (j < e) {
            int s0 = __ldg(&csr[j]);
            uint2 v0 = __ldg(&Y[(size_t)s0 * 16 + f]);
            float2 p0 = __half22float2(*(__half2*)&v0.x);
            float2 p1 = __half22float2(*(__half2*)&v0.y);
            ax += p0.x; ay += p0.y; az += p1.x; aw += p1.y;
        }
        ax += __shfl_xor_sync(0xffffffffu, ax, 16);
        ay += __shfl_xor_sync(0xffffffffu, ay, 16);
        az += __shfl_xor_sync(0xffffffffu, az, 16);
        aw += __shfl_xor_sync(0xffffffffu, aw, 16);
        if (par == 0) {
            float inv = 1.0f / fmaxf((float)(e - b), 1.0f);
            ((float4*)out)[f] = make_float4(ax * inv, ay * inv, az * inv, aw * inv);
        }
    }
}

// ---------------- classifier: 2 label-edges per warp ----------------
__global__ void classify_kernel(const float* __restrict__ hu2, const float* __restrict__ hp2,
                                const int* __restrict__ lu, const int* __restrict__ lp,
                                float* __restrict__ out, int M) {
    int lane = threadIdx.x & 31;
    int warp = (blockIdx.x * blockDim.x + threadIdx.x) >> 5;
    int nw   = (gridDim.x * blockDim.x) >> 5;
    int f = lane & 15, par = lane >> 4;
    for (int e0 = warp * 2; e0 < M; e0 += nw * 2) {
        int e = e0 + par;
        float s = 0.f;
        if (e < M) {
            int u = __ldg(&lu[e]), p = __ldg(&lp[e]);
            float4 a  = __ldg((const float4*)(hu2 + (size_t)u * 64) + f);
            float4 bq = __ldg((const float4*)(hp2 + (size_t)p * 64) + f);
            s = a.x * bq.x + a.y * bq.y + a.z * bq.z + a.w * bq.w;
        }
        s += __shfl_xor_sync(0xffffffffu, s, 8);
        s += __shfl_xor_sync(0xffffffffu, s, 4);
        s += __shfl_xor_sync(0xffffffffu, s, 2);
        s += __shfl_xor_sync(0xffffffffu, s, 1);
        if (f == 0 && e < M) out[e] = s;
    }
}

extern "C" void kernel_launch(void* const* d_in, const int* in_sizes, int n_in,
                              void* d_out, int out_size) {
    const float* x_user    = (const float*)d_in[0];
    const float* x_product = (const float*)d_in[1];
    const float* W1bl = (const float*)d_in[2];
    const float* b1b  = (const float*)d_in[3];
    const float* W1br = (const float*)d_in[4];
    const float* W1rl = (const float*)d_in[5];
    const float* b1r  = (const float*)d_in[6];
    const float* W1rr = (const float*)d_in[7];
    const float* W2bl = (const float*)d_in[8];
    const float* b2b  = (const float*)d_in[9];
    const float* W2br = (const float*)d_in[10];
    const float* W2rl = (const float*)d_in[11];
    const float* b2r  = (const float*)d_in[12];
    const float* W2rr = (const float*)d_in[13];
    const int* esrc = (const int*)d_in[14];
    const int* edst = (const int*)d_in[15];
    const int* lu   = (const int*)d_in[16];
    const int* lp   = (const int*)d_in[17];

    int NU = in_sizes[0] / 64;
    int NP = in_sizes[1] / 128;
    int E  = in_sizes[14];
    int M  = in_sizes[16];
    int NT = NU + NP;

    int *cnt, *rp, *cur, *bsum, *csr;
    __half *yu_h, *yp_h;
    float *aggu, *aggp, *hu, *hp, *hu2, *hp2;
    cudaGetSymbolAddress((void**)&cnt,  g_cnt);
    cudaGetSymbolAddress((void**)&rp,   g_rp);
    cudaGetSymbolAddress((void**)&cur,  g_cur);
    cudaGetSymbolAddress((void**)&bsum, g_bsum);
    cudaGetSymbolAddress((void**)&csr,  g_csr);
    cudaGetSymbolAddress((void**)&yu_h, g_yu_h);
    cudaGetSymbolAddress((void**)&yp_h, g_yp_h);
    cudaGetSymbolAddress((void**)&aggu, g_aggu);
    cudaGetSymbolAddress((void**)&aggp, g_aggp);
    cudaGetSymbolAddress((void**)&hu,   g_hu);
    cudaGetSymbolAddress((void**)&hp,   g_hp);
    cudaGetSymbolAddress((void**)&hu2,  g_hu2);
    cudaGetSymbolAddress((void**)&hp2,  g_hp2);

    int nblkP = (NP + 63) / 64;
    int nblkU = (NU + 63) / 64;
    int nbt   = (NT + SCAN_TILE - 1) / SCAN_TILE;
    int nfill = FILLB_MAX;
    if (nfill > (nblkP + nblkU) / 5) nfill = (nblkP + nblkU) / 5;

    size_t smFat1  = (size_t)(128 * 64 + 128 * XS_STRIDE) * 4;           // 67584
    size_t smFused = (size_t)(128 * 64 + 4096 + 128 * XS_STRIDE) * 4;    // 83968
    size_t smEpi2  = (size_t)(64 * 64 + 64 * XS_STRIDE) * 4;             // 33792

    cudaFuncSetAttribute(gemm_fat1, cudaFuncAttributeMaxDynamicSharedMemorySize, (int)smFat1);
    cudaFuncSetAttribute(gemm_epi_trans, cudaFuncAttributeMaxDynamicSharedMemorySize, (int)smFused);

    // ---- CSR build front half ----
    cudaMemsetAsync(cnt, 0, (size_t)NT * sizeof(int), 0);
    degree_kernel<<<2048, 256>>>(esrc, edst, cnt, NP, E);
    scanA<<<nbt, 256>>>(cnt, bsum, NT);
    scanC2<<<nbt, 256>>>(cnt, bsum, rp, cur, NT, nbt);

    // ---- FAT1: transform-1 (yp = x_p@W1rl, yu = x_u@W1bl) ∪ fill_csr ----
    {
        Seg A = {x_product, W1rl, nullptr, nullptr, nullptr, yp_h, NP, 128, 0};
        Seg B = {x_user,    W1bl, nullptr, nullptr, nullptr, yu_h, NU, 64,  0};
        gemm_fat1<<<nblkP + nblkU + nfill, 256, smFat1>>>(A, B, nblkP,
                                                          esrc, edst, cur, csr, NP, E, nfill);
    }

    gather_mean<<<2048, 256>>>(yu_h, yp_h, csr, rp, aggp, aggu, NP, NT);

    // ---- FUSED: h = relu(agg + x@W1r + b); y2 = h@W2l (fp16) ----
    {
        Seg A = {x_product, W1br, b1b, aggp, hp, nullptr, NP, 128, 1};
        Seg B = {x_user,    W1rr, b1r, aggu, hu, nullptr, NU, 64,  1};
        gemm_epi_trans<<<nblkP + nblkU, 256, smFused>>>(A, B, nblkP,
                                                        W2rl, W2bl, yp_h, yu_h);
    }

    gather_mean<<<2048, 256>>>(yu_h, yp_h, csr, rp, aggp, aggu, NP, NT);

    // ---- epilogue-2 ----
    {
        Seg A = {hp, W2br, b2b, aggp, hp2, nullptr, NP, 64, 0};
        Seg B = {hu, W2rr, b2r, aggu, hu2, nullptr, NU, 64, 0};
        gemm_dual<<<nblkP + nblkU, 256, smEpi2>>>(A, B, nblkP);
    }

    // ---- classifier ----
    classify_kernel<<<4096, 256>>>(hu2, hp2, lu, lp, (float*)d_out, M);
}